// round 17
// baseline (speedup 1.0000x reference)
#include <cuda_runtime.h>
#include <cstdint>

// ---------------------------------------------------------------------------
// local_graph_creator: adj = relu(tanh(3*(vec1@gEmb.T - gEmb@vec1.T))),
// per-row top-20 (value desc, index asc) binary mask applied.
//
// Exact-output structure (rel_err == 0.0 across rounds 1-16): each output row
// is zeros plus satval at the 20 smallest column indices whose tanh saturates
// (bits == satval). Only an exact N x 256 strip of scores is needed; rows
// with <20 saturated strip entries go to an exact full-row fallback.
//
// Round-16 ncu: prep was 27us (reg-bloated, half-chip); fused2's strips-first
// ordering serialized a ~12us strip wave ahead of the 65us zero. Fixes:
//   prep16: 16 rows/block (632 blocks), LDS dot, identical fmaf chain.
//   fused3: strip role interleaved at i%5==2 (zeros co-resident from wave 1)
//           + in-kernel producer-consumer scatter (bounded spin -> fallback).
//
//   default stream: prep16 -> fused3(strip | zero+scatter) -> fallback
// ---------------------------------------------------------------------------

#define MAX_NPAD 10112
#define STRIPW 256

__device__ float g_Xt[128 * MAX_NPAD];     // [k][i]  X = [vec1 | -gEmb]
__device__ float g_Yt[128 * MAX_NPAD];     // [k][i]  Y = [gEmb  |  vec1]
__device__ unsigned g_maskS[MAX_NPAD * 8]; // strip tie bitmask (256 cols/row)
__device__ int g_fb_cnt;
__device__ int g_fb_list[MAX_NPAD];
__device__ int g_strip_done;

__device__ __forceinline__ float tanh_xla(float x) {
    const float kClamp = 7.99881172180175781f;
    float ax = fabsf(x);
    float xc = fminf(fmaxf(x, -kClamp), kClamp);
    float x2 = xc * xc;
    float p = -2.76076847742355e-16f;
    p = fmaf(x2, p, 2.00018790482477e-13f);
    p = fmaf(x2, p, -8.60467152213735e-11f);
    p = fmaf(x2, p, 5.12229709037114e-08f);
    p = fmaf(x2, p, 1.48572235717979e-05f);
    p = fmaf(x2, p, 6.37261928875436e-04f);
    p = fmaf(x2, p, 4.89352455891786e-03f);
    p = xc * p;
    float q = fmaf(x2, 1.19825839466702e-06f, 1.18534705686654e-04f);
    q = fmaf(x2, q, 2.26843463243900e-03f);
    q = fmaf(x2, q, 4.89352518554385e-03f);
    float r = p / q;
    return (ax < 0.0004f) ? x : r;
}

__device__ __forceinline__ float sat_val() { return tanh_xla(8.0f); }

__device__ __forceinline__ void cp_async16(uint32_t saddr, const void* gaddr) {
    asm volatile("cp.async.cg.shared.global [%0], [%1], 16;" ::
                 "r"(saddr), "l"(gaddr));
}

// ---------------------------------------------------------------------------
// prep16: 16 rows per block (npad/16 blocks). Static ~30KB smem, LDS dot
// product with the byte-identical k-ascending fmaf chain.
// ---------------------------------------------------------------------------
__global__ __launch_bounds__(256) void prep16_kernel(
    const int* __restrict__ idx, const float* __restrict__ gEmb,
    const float* __restrict__ embW, const float* __restrict__ fc1w,
    const float* __restrict__ fc1b, int N, int npad) {
    __shared__ float wst[64 * 65];   // [d][k] stride 65
    __shared__ float sv[64 * 17];    // [d][il] stride 17 (vec1^T)
    __shared__ float semb[16 * 64];  // [il][k] gathered emb rows
    __shared__ float sge[64 * 17];   // [d][il] gEmb^T
    __shared__ float bs[64];
    __shared__ int sidx[16];

    const int t = threadIdx.x;
    const int bi0 = blockIdx.x * 16;

    if (blockIdx.x == 0 && t == 0) {
        g_fb_cnt = 0;
        g_strip_done = 0;
    }

    if (t < 64) bs[t] = fc1b[t];
    if (t < 16) {
        int i = bi0 + t;
        sidx[t] = (i < N) ? idx[i] : 0;
    }
    for (int e = t; e < 64 * 64; e += 256) {
        int d = e >> 6, k = e & 63;
        wst[d * 65 + k] = fc1w[e];
    }
    __syncthreads();

    // gathered emb rows (coalesced over k)
    {
        int il = t >> 6, k = t & 63;
#pragma unroll
        for (int u = 0; u < 4; u++) {
            int ill = il + u * 4;
            int i = bi0 + ill;
            semb[ill * 64 + k] =
                (i < N) ? embW[(size_t)sidx[ill] * 64 + k] : 0.0f;
        }
    }
    __syncthreads();

    // vec1: thread (rq, d) handles rows il = rq*4+u; er broadcast, wst s-1
    const int d = t & 63;
    const int rq = t >> 6;
#pragma unroll
    for (int u = 0; u < 4; u++) {
        int il = rq * 4 + u;
        int i = bi0 + il;
        float v = 0.0f;
        if (i < N) {
            const float* er = &semb[il * 64];
            const float* wr = &wst[d * 65];
            float acc = 0.0f;
#pragma unroll
            for (int k = 0; k < 64; k++) acc = fmaf(er[k], wr[k], acc);
            acc += bs[d];
            v = tanh_xla(3.0f * acc);
        }
        sv[d * 17 + il] = v;
    }

    // gEmb^T into sge (read coalesced over dd, scatter into [d][il])
    {
        int il = t >> 6, dd4 = (t & 63);
#pragma unroll
        for (int u = 0; u < 4; u++) {
            int ill = il + u * 4;
            int i = bi0 + ill;
            sge[dd4 * 17 + ill] =
                (i < N) ? gEmb[(size_t)i * 64 + dd4] : 0.0f;
        }
    }
    __syncthreads();

    // pack Xt/Yt: per array 128 dd x 4 float4 = 512 f4; two arrays
#pragma unroll
    for (int p = 0; p < 4; p++) {
        int e = p * 256 + t;       // 0..1023
        int arr = e >> 9;          // 0 = Xt, 1 = Yt
        int rem = e & 511;
        int dd = rem >> 2;         // 0..127
        int i4 = (rem & 3) * 4;    // 0..12
        float4 v;
        if (arr == 0) {
            if (dd < 64) {
                v.x = sv[dd * 17 + i4 + 0]; v.y = sv[dd * 17 + i4 + 1];
                v.z = sv[dd * 17 + i4 + 2]; v.w = sv[dd * 17 + i4 + 3];
            } else {
                int dl = dd - 64;
                v.x = -sge[dl * 17 + i4 + 0]; v.y = -sge[dl * 17 + i4 + 1];
                v.z = -sge[dl * 17 + i4 + 2]; v.w = -sge[dl * 17 + i4 + 3];
            }
            *(float4*)&g_Xt[(size_t)dd * npad + bi0 + i4] = v;
        } else {
            if (dd < 64) {
                v.x = sge[dd * 17 + i4 + 0]; v.y = sge[dd * 17 + i4 + 1];
                v.z = sge[dd * 17 + i4 + 2]; v.w = sge[dd * 17 + i4 + 3];
            } else {
                int dl = dd - 64;
                v.x = sv[dl * 17 + i4 + 0]; v.y = sv[dl * 17 + i4 + 1];
                v.z = sv[dl * 17 + i4 + 2]; v.w = sv[dl * 17 + i4 + 3];
            }
            *(float4*)&g_Yt[(size_t)dd * npad + bi0 + i4] = v;
        }
    }
}

// ---------------------------------------------------------------------------
// fused3: interleaved roles. i%5==2 (si<ns): strip GEMM -> masks -> fence ->
// g_strip_done++. Others: zero 8 full rows, bounded-poll strip_done==ns,
// acquire-fence, scatter own rows (spin expiry -> exact fallback flag).
// ---------------------------------------------------------------------------
__global__ __launch_bounds__(256, 2) void fused3_kernel(
    float* __restrict__ out, int N, int npad, int ns) {
    const int i = blockIdx.x;
    const int t = threadIdx.x;

    if ((i % 5) == 2 && (i - 2) / 5 < ns) {
        const int si = (i - 2) / 5;
        const int bn = (si & 1) * 128;
        const int bm = (si >> 1) * 64;

        extern __shared__ float sm[];
        float* Asf = sm;           // [k][r] 128 x 64
        float* Bsf = sm + 8192;    // [k][r] 128 x 128

        const int tx = t & 15, ty = t >> 4;

        {
            const float4* Xv = reinterpret_cast<const float4*>(g_Xt);
            const float4* Yv = reinterpret_cast<const float4*>(g_Yt);
            uint32_t As_s = (uint32_t)__cvta_generic_to_shared(Asf);
            uint32_t Bs_s = (uint32_t)__cvta_generic_to_shared(Bsf);
            const int np4 = npad >> 2;
            const int bm4 = bm >> 2, bn4 = bn >> 2;
#pragma unroll
            for (int e = 0; e < 8; e++) {
                int q = e * 256 + t;
                int k = q >> 4;
                int r4 = q & 15;
                cp_async16(As_s + q * 16, &Xv[(size_t)k * np4 + bm4 + r4]);
            }
#pragma unroll
            for (int e = 0; e < 16; e++) {
                int q = e * 256 + t;
                int k = q >> 5;
                int r4 = q & 31;
                cp_async16(Bs_s + q * 16, &Yv[(size_t)k * np4 + bn4 + r4]);
            }
            asm volatile("cp.async.commit_group;");
            asm volatile("cp.async.wait_group 0;");
        }
        __syncthreads();

        float acc[4][8];
#pragma unroll
        for (int a = 0; a < 4; a++)
#pragma unroll
            for (int b = 0; b < 8; b++) acc[a][b] = 0.0f;

#pragma unroll 4
        for (int k = 0; k < 128; k++) {
            const float* ak = Asf + k * 64;
            const float* bk = Bsf + k * 128;
            float4 a0 = *(const float4*)(ak + ty * 4);
            float4 b0 = *(const float4*)(bk + tx * 4);
            float4 b1 = *(const float4*)(bk + 64 + tx * 4);
            float ra[4] = {a0.x, a0.y, a0.z, a0.w};
            float rb[8] = {b0.x, b0.y, b0.z, b0.w, b1.x, b1.y, b1.z, b1.w};
#pragma unroll
            for (int a = 0; a < 4; a++)
#pragma unroll
                for (int b = 0; b < 8; b++)
                    acc[a][b] = fmaf(ra[a], rb[b], acc[a][b]);
        }

#pragma unroll
        for (int a = 0; a < 4; a++)
#pragma unroll
            for (int b = 0; b < 8; b++) acc[a][b] = tanh_xla(3.0f * acc[a][b]);

        __syncthreads();  // As/Bs dead

        unsigned* mUw = reinterpret_cast<unsigned*>(sm);  // [64][32] nibbles
        const unsigned satb = __float_as_uint(sat_val());

#pragma unroll
        for (int ii = 0; ii < 4; ii++) {
            int r = ty * 4 + ii;
#pragma unroll
            for (int q = 0; q < 2; q++) {
                unsigned nib = 0;
#pragma unroll
                for (int b = 0; b < 4; b++)
                    nib |= (__float_as_uint(acc[ii][q * 4 + b]) == satb) << b;
                mUw[r * 32 + 16 * q + tx] = nib;
            }
        }
        __syncthreads();

        {
            int r = t >> 2, ww = t & 3;
            unsigned wd = 0;
#pragma unroll
            for (int b = 0; b < 8; b++)
                wd |= mUw[r * 32 + ww * 8 + b] << (4 * b);
            g_maskS[(size_t)(bm + r) * 8 + (bn >> 5) + ww] = wd;
        }

        __threadfence();
        __syncthreads();
        if (t == 0) atomicAdd(&g_strip_done, 1);
    } else {
        // zero + scatter role
        __shared__ int sok;
        const int zi = i - (i + 2) / 5 - ((i % 5) == 2 ? 1 : 0);
        const int row = zi * 8 + (t >> 5);
        const int lane = t & 31;

        if (row < N) {
            float* rowp = out + (size_t)row * N;
            const int nv = N >> 2;
            const float4 z = make_float4(0.0f, 0.0f, 0.0f, 0.0f);
            for (int q = lane; q < nv; q += 32)
                reinterpret_cast<float4*>(rowp)[q] = z;
            for (int q = nv * 4 + lane; q < N; q += 32) rowp[q] = 0.0f;
        }

        if (t == 0) {
            int ok = 1, spins = 0;
            while (atomicAdd(&g_strip_done, 0) < ns) {
                __nanosleep(64);
                if (++spins > (1 << 18)) { ok = 0; break; }
            }
            sok = ok;
        }
        __syncthreads();
        __threadfence();  // acquire

        if (row < N) {
            if (sok) {
                unsigned w =
                    (lane < 8) ? g_maskS[(size_t)row * 8 + lane] : 0u;
                int c = __popc(w);
                int incl = c;
#pragma unroll
                for (int s = 1; s < 32; s <<= 1) {
                    int o = __shfl_up_sync(0xffffffffu, incl, s);
                    if (lane >= s) incl += o;
                }
                int excl = incl - c;
                int total = __shfl_sync(0xffffffffu, incl, 31);

                if (total >= 20) {
                    const float sv = sat_val();
                    float* rowp = out + (size_t)row * N;
                    int base = excl;
                    unsigned ww = w;
                    while (ww && base < 20) {
                        int b = __ffs(ww) - 1;
                        ww &= ww - 1;
                        rowp[lane * 32 + b] = sv;
                        base++;
                    }
                } else if (lane == 0) {
                    int p = atomicAdd(&g_fb_cnt, 1);
                    g_fb_list[p] = row;
                }
            } else if (lane == 0) {
                int p = atomicAdd(&g_fb_cnt, 1);
                g_fb_list[p] = row;
            }
        }
    }
}

// ---------------------------------------------------------------------------
// fallback: exact full-row recompute + general top-20 (expected 0 rows).
// ---------------------------------------------------------------------------
__global__ __launch_bounds__(256) void fallback_kernel(float* __restrict__ out,
                                                       int N, int npad) {
    __shared__ float sX[128];
    __shared__ __align__(16) float srow[10016];
    __shared__ unsigned long long red[256];
    __shared__ int selIdx[20];
    __shared__ float selVal[20];

    const int t = threadIdx.x;
    const int cnt = g_fb_cnt;

    for (int ri = blockIdx.x; ri < cnt; ri += gridDim.x) {
        const int row = g_fb_list[ri];
        if (t < 128) sX[t] = g_Xt[(size_t)t * npad + row];
        __syncthreads();

        for (int j = t; j < N; j += 256) {
            float a = 0.0f;
#pragma unroll 4
            for (int k = 0; k < 128; k++)
                a = fmaf(sX[k], g_Yt[(size_t)k * npad + j], a);
            srow[j] = fmaxf(tanh_xla(3.0f * a), 0.0f);
        }
        __syncthreads();

        // clear the row first (it may hold partial scatter state)
        for (int j = t; j < N; j += 256) out[(size_t)row * N + j] = 0.0f;

        unsigned long long cand[20];
#pragma unroll
        for (int c = 0; c < 20; c++) cand[c] = 0ull;
        unsigned long long curMin = 0ull;
        for (int q = t; q < N; q += 256) {
            unsigned vb = __float_as_uint(srow[q]);
            if (vb == 0x80000000u) vb = 0u;
            unsigned long long key =
                ((unsigned long long)vb << 32) |
                (unsigned long long)(0xFFFFFFFFu - (unsigned)q);
            if (key > curMin) {
                bool done = false;
#pragma unroll
                for (int c = 0; c < 20; c++) {
                    if (!done && cand[c] == curMin) {
                        cand[c] = key;
                        done = true;
                    }
                }
                unsigned long long m = cand[0];
#pragma unroll
                for (int c = 1; c < 20; c++) m = (cand[c] < m) ? cand[c] : m;
                curMin = m;
            }
        }
        for (int it = 0; it < 20; it++) {
            unsigned long long m = cand[0];
#pragma unroll
            for (int c = 1; c < 20; c++) m = (cand[c] > m) ? cand[c] : m;
            red[t] = m;
            __syncthreads();
            for (int s = 128; s >= 32; s >>= 1) {
                if (t < s) {
                    unsigned long long o = red[t + s];
                    if (o > red[t]) red[t] = o;
                }
                __syncthreads();
            }
            if (t < 32) {
                unsigned long long g = red[t];
#pragma unroll
                for (int s = 16; s; s >>= 1) {
                    unsigned long long o = __shfl_xor_sync(0xffffffffu, g, s);
                    if (o > g) g = o;
                }
                if (t == 0) red[0] = g;
            }
            __syncthreads();
            unsigned long long g = red[0];
            if (t == 0) {
                if (g != 0ull) {
                    selIdx[it] =
                        (int)(0xFFFFFFFFu - (unsigned)(g & 0xFFFFFFFFull));
                    selVal[it] = __uint_as_float((unsigned)(g >> 32));
                } else {
                    selIdx[it] = 0;
                    selVal[it] = 0.0f;
                }
            }
            if (g != 0ull) {
#pragma unroll
                for (int c = 0; c < 20; c++)
                    if (cand[c] == g) cand[c] = 0ull;
            }
            __syncthreads();
        }
        if (t < 20) out[(size_t)row * N + selIdx[t]] = selVal[t];
        __syncthreads();
    }
}

// ---------------------------------------------------------------------------
extern "C" void kernel_launch(void* const* d_in, const int* in_sizes, int n_in,
                              void* d_out, int out_size) {
    const int* idx = (const int*)d_in[0];
    const float* gEmb = (const float*)d_in[1];
    const float* embW = (const float*)d_in[2];
    const float* fc1w = (const float*)d_in[3];
    const float* fc1b = (const float*)d_in[4];
    float* out = (float*)d_out;

    int N = in_sizes[0];
    int npad = ((N + 127) / 128) * 128;
    int tiles64 = npad / 64;
    int ns = 2 * tiles64;          // strip blocks
    int total = 5 * ns;            // zero slots = 4*ns = npad/8 >= ceil(N/8)

    static bool s_init = false;
    if (!s_init) {
        cudaFuncSetAttribute(fused3_kernel,
                             cudaFuncAttributeMaxDynamicSharedMemorySize,
                             98304);
        s_init = true;
    }

    prep16_kernel<<<npad / 16, 256>>>(idx, gEmb, embW, fc1w, fc1b, N, npad);
    fused3_kernel<<<total, 256, 98304>>>(out, N, npad, ns);
    fallback_kernel<<<16, 256>>>(out, N, npad);
}